// round 13
// baseline (speedup 1.0000x reference)
#include <cuda_runtime.h>
#include <cstdint>

// Problem constants
namespace {
constexpr int BATCH = 2, L = 2048, S = 2048, H = 8, E = 64;
constexpr int BM = 64;          // query rows per block (4 warps x m16)
constexpr int BN = 64;          // keys per chunk
constexpr int THREADS = 128;    // 4 warps
constexpr size_t OFF_A   = (size_t)BATCH * L * H * E;
constexpr size_t OFF_ENT = OFF_A + (size_t)BATCH * H * L * S;
constexpr float SCALE = 0.125f;   // 1/sqrt(64), exact power of 2
// smem layout (bytes): K double-buffered, V+mask single-buffered
constexpr int TILE_B   = 64 * 144;          // 9216 (one hi or lo tile)
constexpr int KST_B    = 2 * TILE_B;        // 18432 (Kh+Kl per stage)
constexpr int V_OFF    = 2 * KST_B;         // 36864
constexpr int MSK_OFF  = V_OFF + KST_B;     // 55296
constexpr int SMEM_TOT = MSK_OFF + 64 * 4;  // 55552
}

// Scratch (no device allocation allowed -> __device__ globals)
__device__ int g_layout;                  // 0=int32, 1=float32, 2=uint8 mask storage
__device__ unsigned char g_mq[BATCH * L];
__device__ __align__(16) float g_mkf[BATCH * S];   // key mask as 0/1 float
__device__ float g_rf[BATCH * H * L];     // per-row final scale qf/sum
// Pre-split bf16 hi/lo K and V, layout [b][h][s][e], bf16x2 packed in u32
__device__ uint32_t g_Kh[BATCH * H * S * E / 2];
__device__ uint32_t g_Kl[BATCH * H * S * E / 2];
__device__ uint32_t g_Vh[BATCH * H * S * E / 2];
__device__ uint32_t g_Vl[BATCH * H * S * E / 2];

// ---------------------------------------------------------------------------
// PTX helpers
// ---------------------------------------------------------------------------
__device__ __forceinline__ uint32_t smem_u32(const void* p) {
    uint32_t a;
    asm("{.reg .u64 t; cvta.to.shared.u64 t, %1; cvt.u32.u64 %0, t;}" : "=r"(a) : "l"(p));
    return a;
}
__device__ __forceinline__ void ldsm4(uint32_t* r, uint32_t addr) {
    asm volatile("ldmatrix.sync.aligned.m8n8.x4.shared.b16 {%0,%1,%2,%3}, [%4];"
        : "=r"(r[0]), "=r"(r[1]), "=r"(r[2]), "=r"(r[3]) : "r"(addr));
}
__device__ __forceinline__ void ldsm4t(uint32_t* r, uint32_t addr) {
    asm volatile("ldmatrix.sync.aligned.m8n8.x4.trans.shared.b16 {%0,%1,%2,%3}, [%4];"
        : "=r"(r[0]), "=r"(r[1]), "=r"(r[2]), "=r"(r[3]) : "r"(addr));
}
__device__ __forceinline__ void mma_bf16(float* d, const uint32_t* a, uint32_t b0, uint32_t b1) {
    asm volatile("mma.sync.aligned.m16n8k16.row.col.f32.bf16.bf16.f32 "
        "{%0,%1,%2,%3},{%4,%5,%6,%7},{%8,%9},{%0,%1,%2,%3};"
        : "+f"(d[0]), "+f"(d[1]), "+f"(d[2]), "+f"(d[3])
        : "r"(a[0]), "r"(a[1]), "r"(a[2]), "r"(a[3]), "r"(b0), "r"(b1));
}
// pack (x -> low bf16, y -> high bf16) of hi parts + residual lo parts
__device__ __forceinline__ void splitpack(float x, float y, uint32_t& h, uint32_t& lo) {
    asm("cvt.rn.bf16x2.f32 %0, %1, %2;" : "=r"(h) : "f"(y), "f"(x));
    float xh = __uint_as_float(h << 16);
    float yh = __uint_as_float(h & 0xFFFF0000u);
    asm("cvt.rn.bf16x2.f32 %0, %1, %2;" : "=r"(lo) : "f"(y - yh), "f"(x - xh));
}
__device__ __forceinline__ void cpa16(uint32_t dst, const void* src) {
    asm volatile("cp.async.cg.shared.global [%0], [%1], 16;" :: "r"(dst), "l"(src));
}
#define CP_COMMIT() asm volatile("cp.async.commit_group;")
#define CP_WAIT0()  asm volatile("cp.async.wait_group 0;")
#define CP_WAIT1()  asm volatile("cp.async.wait_group 1;")

// ---------------------------------------------------------------------------
// Mask dtype detection (reads 4096 bytes, in-bounds for every candidate layout)
// ---------------------------------------------------------------------------
__global__ void detect_kernel(const unsigned int* __restrict__ mk) {
    __shared__ int flags[2];
    if (threadIdx.x == 0) { flags[0] = 0; flags[1] = 0; }
    __syncthreads();
    int notint = 0, notfloat = 0;
    for (int i = threadIdx.x; i < 1024; i += blockDim.x) {
        unsigned v = mk[i];
        if (v > 1u) notint = 1;
        if (v != 0u && v != 0x3F800000u) notfloat = 1;
    }
    if (notint)   atomicOr(&flags[0], 1);
    if (notfloat) atomicOr(&flags[1], 1);
    __syncthreads();
    if (threadIdx.x == 0)
        g_layout = (!flags[0]) ? 0 : ((!flags[1]) ? 1 : 2);
}

__global__ void expand_kernel(const void* __restrict__ mk, const void* __restrict__ mq) {
    const int lay = g_layout;
    int i = blockIdx.x * blockDim.x + threadIdx.x;
    if (i < BATCH * S) {
        bool m;
        if (lay == 0)      m = (((const int*)mk)[i] != 0);
        else if (lay == 1) m = (((const float*)mk)[i] != 0.0f);
        else               m = (((const unsigned char*)mk)[i] != 0);
        g_mkf[i] = m ? 0.0f : 1.0f;     // multiplicative keep-factor
    }
    if (i < BATCH * L) {
        unsigned char v;
        if (lay == 0)      v = (((const int*)mq)[i] != 0);
        else if (lay == 1) v = (((const float*)mq)[i] != 0.0f);
        else               v = (((const unsigned char*)mq)[i] != 0);
        g_mq[i] = v;
    }
}

// ---------------------------------------------------------------------------
// Prep: split K/V fp32 [b,s,h,e] -> hi/lo bf16x2 [b,h,s,e] (row-contiguous)
// ---------------------------------------------------------------------------
__global__ void prep_kernel(const float* __restrict__ K, const float* __restrict__ V) {
    int t = blockIdx.x * blockDim.x + threadIdx.x;     // 0 .. 2M/4-1
    const float* src = blockIdx.y ? V : K;
    uint32_t* dh = blockIdx.y ? g_Vh : g_Kh;
    uint32_t* dl = blockIdx.y ? g_Vl : g_Kl;
    int e4 = t * 4;                                    // linear elem index (input layout)
    int e  = e4 & (E - 1);
    int h  = (e4 >> 6) & (H - 1);
    int s  = (e4 >> 9) & (S - 1);
    int b  = e4 >> 20;
    float4 v = *(const float4*)(src + e4);
    uint32_t h0, l0, h1, l1;
    splitpack(v.x, v.y, h0, l0);
    splitpack(v.z, v.w, h1, l1);
    size_t oe = (((size_t)(b * H + h) * S + s) * E + e) >> 1;   // u32 index
    *(uint2*)(dh + oe) = make_uint2(h0, h1);
    *(uint2*)(dl + oe) = make_uint2(l0, l1);
}

// ---------------------------------------------------------------------------
// Stage a 64x64 fp32 gmem tile into hi/lo bf16 smem tiles, scaled (Q prologue)
// ---------------------------------------------------------------------------
__device__ __forceinline__ void stage_q(const float* __restrict__ gbase,
                                        uint32_t* th, uint32_t* tl, int tid) {
#pragma unroll
    for (int it = 0; it < 16; it++) {
        int fi = it * THREADS + tid;
        int r = fi >> 5, cp = fi & 31;
        float2 v = *(const float2*)(gbase + (size_t)r * (H * E) + 2 * cp);
        uint32_t h, lo;
        splitpack(v.x * SCALE, v.y * SCALE, h, lo);
        th[r * 36 + cp] = h;
        tl[r * 36 + cp] = lo;
    }
}

// ---------------------------------------------------------------------------
// Fused pass: K double-buffered / V single-buffered cp.async pipeline,
// tensor-core QK^T -> e=exp(l) (masked->0) -> A region + register P-frags
// -> tensor-core PV; analytic entropy; per-row rescale factor.
// ---------------------------------------------------------------------------
__global__ void __launch_bounds__(THREADS, 4) fused_kernel(
    const float* __restrict__ Q, float* __restrict__ out,
    const int* __restrict__ causal_ptr)
{
    extern __shared__ char smem[];
    const uint32_t base = smem_u32(smem);

    const int b  = blockIdx.z, h = blockIdx.y;
    const int bh = b * H + h;
    const int i0 = (gridDim.x - 1 - blockIdx.x) * BM;   // heavy blocks first
    const int tid  = threadIdx.x;
    const int wm   = tid >> 5;
    const int lane = tid & 31;
    const int gl = lane >> 2, tt = lane & 3;
    const int causal = causal_ptr ? (causal_ptr[0] != 0) : 1;

    const int i_g  = i0 + wm * 16 + gl;
    const int i_g8 = i_g + 8;
    const int w_row_max = i0 + wm * 16 + 15;

    // ---- prologue: stage scaled Q through stage-0 K area, frags to regs ----
    stage_q(Q + (((size_t)b * L + i0) * H + h) * E,
            (uint32_t*)smem, (uint32_t*)(smem + TILE_B), tid);
    __syncthreads();
    const uint32_t offQ = (uint32_t)((wm * 16 + (lane & 15)) * 144 + (lane >> 4) * 16);
    uint32_t qh[4][4], ql[4][4];
#pragma unroll
    for (int ks = 0; ks < 4; ks++) {
        ldsm4(qh[ks], base + offQ + ks * 32);
        ldsm4(ql[ks], base + TILE_B + offQ + ks * 32);
    }
    __syncthreads();   // Q frags read; smem free for pipeline

    float o[8][4];
    float s0 = 0.f, s1 = 0.f, el0 = 0.f, el1 = 0.f;
#pragma unroll
    for (int nt = 0; nt < 8; nt++)
#pragma unroll
        for (int q = 0; q < 4; q++) o[nt][q] = 0.f;

    const uint32_t offK = (uint32_t)((((lane & 16) ? 8 : 0) + (lane & 7)) * 144 + ((lane & 8) ? 16 : 0));
    const uint32_t offV = (uint32_t)((((lane & 8) ? 8 : 0) + (lane & 7)) * 144 + (((lane & 16) ? 8 : 0)) * 2);

    const int jlim = causal ? (i0 + BM < S ? i0 + BM : S) : S;
    const int nch = jlim / BN;

    const int seg = tid & 7;            // 16B segment within 128B row
    const int rg  = tid >> 3;           // row group 0..15

    auto prefetch_k = [&](int j0, int st) {
        uint32_t dst = base + st * KST_B + rg * 144 + seg * 16;
        size_t srcb = ((size_t)bh * S + j0 + rg) * (E / 2) + seg * 4;   // u32 idx
#pragma unroll
        for (int it = 0; it < 4; it++) {
            cpa16(dst,          g_Kh + srcb);
            cpa16(dst + TILE_B, g_Kl + srcb);
            dst  += 16 * 144;
            srcb += 16 * (E / 2);
        }
    };
    auto prefetch_v = [&](int j0) {
        uint32_t dst = base + V_OFF + rg * 144 + seg * 16;
        size_t srcb = ((size_t)bh * S + j0 + rg) * (E / 2) + seg * 4;
#pragma unroll
        for (int it = 0; it < 4; it++) {
            cpa16(dst,          g_Vh + srcb);
            cpa16(dst + TILE_B, g_Vl + srcb);
            dst  += 16 * 144;
            srcb += 16 * (E / 2);
        }
        if (tid < 16) cpa16(base + MSK_OFF + tid * 16, g_mkf + b * S + j0 + tid * 4);
    };

    prefetch_k(0, 0);
    CP_COMMIT();
    int cur = 0;

    for (int ci = 0; ci < nch; ci++) {
        const int j0 = ci * BN;
        CP_WAIT0();          // K(ci) (and everything older) arrived
        __syncthreads();     // all warps past prior PV -> V buffer reusable
        prefetch_v(j0);
        CP_COMMIT();                                    // group A: V + mask
        if (ci + 1 < nch) prefetch_k(j0 + BN, cur ^ 1);
        CP_COMMIT();                                    // group B: next K (may be empty)

        const bool active = !(causal && j0 > w_row_max);
        float e[8][4];

        if (active) {
            const uint32_t aKh = base + cur * KST_B;
            const uint32_t aKl = aKh + TILE_B;
            // ---- QK^T: 3-mma bf16 hi/lo (Q pre-scaled -> outputs are logits) ----
#pragma unroll
            for (int nt = 0; nt < 8; nt++)
#pragma unroll
                for (int q = 0; q < 4; q++) e[nt][q] = 0.f;
#pragma unroll
            for (int ks = 0; ks < 4; ks++) {
#pragma unroll
                for (int np = 0; np < 4; np++) {
                    uint32_t bhf[4], blf[4];
                    ldsm4(bhf, aKh + offK + (uint32_t)(np * 16 * 144) + ks * 32);
                    ldsm4(blf, aKl + offK + (uint32_t)(np * 16 * 144) + ks * 32);
                    mma_bf16(e[2 * np],     qh[ks], bhf[0], bhf[1]);
                    mma_bf16(e[2 * np],     ql[ks], bhf[0], bhf[1]);
                    mma_bf16(e[2 * np],     qh[ks], blf[0], blf[1]);
                    mma_bf16(e[2 * np + 1], qh[ks], bhf[2], bhf[3]);
                    mma_bf16(e[2 * np + 1], ql[ks], bhf[2], bhf[3]);
                    mma_bf16(e[2 * np + 1], qh[ks], blf[2], blf[3]);
                }
            }
        }

        CP_WAIT1();          // group A (V+mask) done; next-K may still be in flight
        __syncthreads();     // V/mask visible to all warps

        if (active) {
            const float* s_mkf = (const float*)(smem + MSK_OFF);
            // ---- softmax numerators ----
#pragma unroll
            for (int nt = 0; nt < 8; nt++) {
                int jc = j0 + nt * 8 + 2 * tt;
                float2 mk2 = *(const float2*)&s_mkf[nt * 8 + 2 * tt];
                float l00 = e[nt][0], l01 = e[nt][1];
                float l10 = e[nt][2], l11 = e[nt][3];
                float e00 = (!causal || jc     <= i_g ) ? __expf(l00) * mk2.x : 0.f;
                float e01 = (!causal || jc + 1 <= i_g ) ? __expf(l01) * mk2.y : 0.f;
                float e10 = (!causal || jc     <= i_g8) ? __expf(l10) * mk2.x : 0.f;
                float e11 = (!causal || jc + 1 <= i_g8) ? __expf(l11) * mk2.y : 0.f;
                s0  += e00 + e01;             s1  += e10 + e11;
                el0 += e00 * l00 + e01 * l01; el1 += e10 * l10 + e11 * l11;
                size_t ab = OFF_A + ((size_t)(bh * L + i_g)) * S + jc;
                *(float2*)&out[ab]                 = make_float2(e00, e01);
                *(float2*)&out[ab + 8 * (size_t)S] = make_float2(e10, e11);
                e[nt][0] = e00; e[nt][1] = e01; e[nt][2] = e10; e[nt][3] = e11;
            }
            // ---- PV: P-frags from registers, V hi/lo ----
#pragma unroll
            for (int ks = 0; ks < 4; ks++) {
                uint32_t ph[4], pl[4];
                splitpack(e[2 * ks][0],     e[2 * ks][1],     ph[0], pl[0]);
                splitpack(e[2 * ks][2],     e[2 * ks][3],     ph[1], pl[1]);
                splitpack(e[2 * ks + 1][0], e[2 * ks + 1][1], ph[2], pl[2]);
                splitpack(e[2 * ks + 1][2], e[2 * ks + 1][3], ph[3], pl[3]);
#pragma unroll
                for (int np = 0; np < 4; np++) {
                    uint32_t vh[4], vl[4];
                    uint32_t av = base + V_OFF + offV + (uint32_t)(ks * 16 * 144) + (uint32_t)(np * 32);
                    ldsm4t(vh, av);
                    ldsm4t(vl, av + TILE_B);
                    mma_bf16(o[2 * np],     ph, vh[0], vh[1]);
                    mma_bf16(o[2 * np],     pl, vh[0], vh[1]);
                    mma_bf16(o[2 * np],     ph, vl[0], vl[1]);
                    mma_bf16(o[2 * np + 1], ph, vh[2], vh[3]);
                    mma_bf16(o[2 * np + 1], pl, vh[2], vh[3]);
                    mma_bf16(o[2 * np + 1], ph, vl[2], vl[3]);
                }
            }
        }
        cur ^= 1;
    }

    // ---- epilogue ----
#pragma unroll
    for (int off = 1; off <= 2; off <<= 1) {
        s0  += __shfl_xor_sync(0xffffffffu, s0,  off);
        s1  += __shfl_xor_sync(0xffffffffu, s1,  off);
        el0 += __shfl_xor_sync(0xffffffffu, el0, off);
        el1 += __shfl_xor_sync(0xffffffffu, el1, off);
    }
    float qf0 = g_mq[b * L + i_g ] ? 0.f : 1.f;
    float qf1 = g_mq[b * L + i_g8] ? 0.f : 1.f;
    float rf0 = qf0 / s0, rf1 = qf1 / s1;
    if (tt == 0) {
        int idx0 = bh * L + i_g;
        int idx1 = idx0 + 8;
        g_rf[idx0] = rf0;
        g_rf[idx1] = rf1;
        out[OFF_ENT + idx0] = qf0 * (__logf(s0) - el0 / s0);
        out[OFF_ENT + idx1] = qf1 * (__logf(s1) - el1 / s1);
    }
    size_t vb0 = (((size_t)b * L + i_g ) * H + h) * E + 2 * tt;
    size_t vb1 = (((size_t)b * L + i_g8) * H + h) * E + 2 * tt;
#pragma unroll
    for (int nt = 0; nt < 8; nt++) {
        *(float2*)&out[vb0 + nt * 8] = make_float2(o[nt][0] * rf0, o[nt][1] * rf0);
        *(float2*)&out[vb1 + nt * 8] = make_float2(o[nt][2] * rf1, o[nt][3] * rf1);
    }
}

// ---------------------------------------------------------------------------
// Streaming rescale: A <- e * rf(row); beyond-causal region written as 0.
// ---------------------------------------------------------------------------
__global__ void __launch_bounds__(256) scale_kernel(
    float* __restrict__ out, const int* __restrict__ causal_ptr)
{
    const int r = blockIdx.x;
    const int i = r & (L - 1);
    const int causal = causal_ptr ? (causal_ptr[0] != 0) : 1;
    const int live = causal ? i + 1 : S;
    const float rf = g_rf[r];
    const size_t base = OFF_A + (size_t)r * S;
    const int t = threadIdx.x;
#pragma unroll
    for (int k = 0; k < 2; k++) {
        int j = (t + 256 * k) * 4;
        float4 v;
        if (j < live) {
            v = *(const float4*)&out[base + j];
            v.x = (j + 0 < live) ? v.x * rf : 0.0f;
            v.y = (j + 1 < live) ? v.y * rf : 0.0f;
            v.z = (j + 2 < live) ? v.z * rf : 0.0f;
            v.w = (j + 3 < live) ? v.w * rf : 0.0f;
        } else {
            v = make_float4(0.f, 0.f, 0.f, 0.f);
        }
        *(float4*)&out[base + j] = v;
    }
}

// ---------------------------------------------------------------------------
extern "C" void kernel_launch(void* const* d_in, const int* in_sizes, int n_in,
                              void* d_out, int out_size) {
    const float* q  = (const float*)d_in[0];
    const float* k  = (const float*)d_in[1];
    const float* v  = (const float*)d_in[2];
    const void*  mk = d_in[3];
    const void*  mq = d_in[4];
    const int* causal = (n_in >= 7) ? (const int*)d_in[6] : nullptr;
    float* out = (float*)d_out;

    // Unconditional (no static guards allowed): idempotent host-side attribute.
    cudaFuncSetAttribute(fused_kernel,
                         cudaFuncAttributeMaxDynamicSharedMemorySize, SMEM_TOT);

    detect_kernel<<<1, 256>>>((const unsigned int*)mk);
    expand_kernel<<<(BATCH * S + 255) / 256, 256>>>(mk, mq);
    prep_kernel<<<dim3(BATCH * S * H * E / 4 / 256, 2), 256>>>(k, v);

    dim3 grid(L / BM, H, BATCH);
    fused_kernel<<<grid, THREADS, SMEM_TOT>>>(q, out, causal);
    scale_kernel<<<BATCH * H * L, 256>>>(out, causal);
}